// round 15
// baseline (speedup 1.0000x reference)
#include <cuda_runtime.h>
#include <cuda_fp16.h>
#include <mma.h>
#include <math.h>

using namespace nvcuda;

#define NN 50000
#define NE 800000
#define NG 500
#define CC 64
#define NL 13          // 1 + 12 PDN convs

// modes for k_agg epilogue
#define M_COPY  1
#define M_SKIP  2
#define M_POOL  8

// ---------------- scratch (device globals; no allocation) ----------------
__device__ __half g_h  [NN*CC];     // fp16 GEMM output (gather bandwidth halved)
__device__ float  g_cur[NN*CC];
__device__ float  g_acc[NN*CC];
__device__ float  g_ew [NL*NE];     // raw ew (CSR order) -> scaled to ew*dis_src in k_norm
__device__ float  g_deg[NN*16];     // [node][16] degree (raw; rsqrt applied at use sites)
__device__ int    g_cnt[NN];        // zero at entry (static init / re-zeroed by k_norm)
__device__ int    g_rowptr[NN+1];
__device__ int    g_cursor[NN];
__device__ __align__(16) int2 g_epack[NE];   // {eid, dst} in CSR order
__device__ int    g_csrc[NE];
__device__ float  g_colsum[13*64];  // fp32 BN stats (zeroed in k_scanall)
__device__ float  g_colsq [13*64];
__device__ float  g_pool[NG*CC];    // zeroed in k_scanall

// ---------------- CSR build ----------------
// NE == 3125*256 exactly; also NE == NN*16, so this thread grid covers g_deg init.
__global__ void k_hist(const int* __restrict__ dst) {
    int e = blockIdx.x*blockDim.x + threadIdx.x;
    g_deg[e] = 1.0f;                 // deg starts at self-loop weight 1
    atomicAdd(&g_cnt[dst[e]], 1);    // g_cnt zero at entry
}

// single-block chunked scan: 1024 threads, 49 chunks; also zeroes pool/stats
__global__ void k_scanall() {
    __shared__ int wsum[32];
    int t = threadIdx.x;
    for (int i = t; i < NG*CC; i += 1024) g_pool[i] = 0.0f;
    for (int i = t; i < 13*64; i += 1024) { g_colsum[i] = 0.0f; g_colsq[i] = 0.0f; }
    int lane = t & 31, wid = t >> 5;
    int carry = 0;
    for (int base = 0; base < NN; base += 1024) {
        int i = base + t;
        int v = (i < NN) ? g_cnt[i] : 0;
        int x = v;
        #pragma unroll
        for (int off = 1; off < 32; off <<= 1) {
            int u = __shfl_up_sync(0xffffffffu, x, off);
            if (lane >= off) x += u;
        }
        if (lane == 31) wsum[wid] = x;
        __syncthreads();
        if (wid == 0) {
            int y = wsum[lane];
            #pragma unroll
            for (int off = 1; off < 32; off <<= 1) {
                int u = __shfl_up_sync(0xffffffffu, y, off);
                if (lane >= off) y += u;
            }
            wsum[lane] = y;
        }
        __syncthreads();
        int pre = (wid > 0) ? wsum[wid-1] : 0;
        int excl = carry + pre + x - v;
        if (i < NN) { g_rowptr[i] = excl; g_cursor[i] = excl; }
        int tot = wsum[31];
        __syncthreads();
        carry += tot;
    }
    if (t == 0) g_rowptr[NN] = carry;
}

__global__ void k_scatter(const int* __restrict__ src, const int* __restrict__ dst) {
    int e = blockIdx.x*blockDim.x + threadIdx.x;
    if (e >= NE) return;
    int d = dst[e];
    int p = atomicAdd(&g_cursor[d], 1);
    int2 pk; pk.x = e; pk.y = d;
    g_epack[p] = pk;
    g_csrc[p]  = src[e];
}

// ---------------- edge MLPs via tensor cores ----------------
// warp = one 16-edge tile; A-frag (16 edges x 16 feats, fp16) built once, reused
// for all 13 layers. Per layer: 1 wmma vs W1_l -> fp32 C in smem -> fp32
// bias+relu+dot(w2)+b2 -> sigmoid. 2 lanes per edge (8 hidden units each).
__global__ __launch_bounds__(256) void k_edgemlp(
    const float* __restrict__ ea,
    const float* __restrict__ m1W, const float* __restrict__ m1b,
    const float* __restrict__ m2W, const float* __restrict__ m2b,
    const float* __restrict__ hm1W, const float* __restrict__ hm1b,
    const float* __restrict__ hm2W, const float* __restrict__ hm2b)
{
    __shared__ __align__(32) __half sW1[NL*256];   // W1[l][i*16+j] row-major (in x hidden)
    __shared__ float sb1[NL*16], sw2[NL*16], sb2[NL];
    __shared__ __align__(32) __half sA[8][256];    // per-warp 16x16 fp16 edge tile
    __shared__ __align__(32) float  sC[8][256];    // per-warp 16x16 fp32 hidden staging

    int t = threadIdx.x;
    for (int idx = t; idx < NL*256; idx += 256) {
        int l = idx >> 8, r = idx & 255;
        float v = (l == 0) ? m1W[r] : hm1W[(l-1)*256 + r];
        sW1[idx] = __float2half(v);
    }
    if (t < NL*16) {
        int l = t >> 4, r = t & 15;
        sb1[t] = (l == 0) ? m1b[r] : hm1b[(l-1)*16 + r];
        sw2[t] = (l == 0) ? m2W[r] : hm2W[(l-1)*16 + r];
    }
    if (t < NL) sb2[t] = (t == 0) ? m2b[0] : hm2b[t-1];
    __syncthreads();

    int w = t >> 5, lane = t & 31;
    int tile = blockIdx.x*8 + w;         // 6250 blocks x 8 warps = 50000 tiles (exact)
    int p0 = tile*16;
    int e = lane >> 1, half = lane & 1;  // 2 lanes per edge
    int pe = p0 + e;

    int2 pk = g_epack[pe];
    int eid = pk.x, dd = pk.y;

    // build fp16 A tile: each lane covers 8 feats of its edge
    {
        const float4* ap = (const float4*)(ea + (size_t)eid*16 + half*8);
        float4 v0 = ap[0], v1 = ap[1];
        __half2 h0 = __floats2half2_rn(v0.x, v0.y);
        __half2 h1 = __floats2half2_rn(v0.z, v0.w);
        __half2 h2 = __floats2half2_rn(v1.x, v1.y);
        __half2 h3 = __floats2half2_rn(v1.z, v1.w);
        uint4 u;
        u.x = *(unsigned*)&h0; u.y = *(unsigned*)&h1;
        u.z = *(unsigned*)&h2; u.w = *(unsigned*)&h3;
        *(uint4*)(&sA[w][e*16 + half*8]) = u;
    }
    __syncwarp();

    wmma::fragment<wmma::matrix_a, 16, 16, 16, __half, wmma::row_major> af;
    wmma::load_matrix_sync(af, sA[w], 16);

    #pragma unroll 1
    for (int l = 0; l < NL; l++) {
        wmma::fragment<wmma::matrix_b, 16, 16, 16, __half, wmma::row_major> bf;
        wmma::load_matrix_sync(bf, sW1 + l*256, 16);
        wmma::fragment<wmma::accumulator, 16, 16, 16, float> cf;
        wmma::fill_fragment(cf, 0.0f);
        wmma::mma_sync(cf, af, bf, cf);
        wmma::store_matrix_sync(sC[w], cf, 16, wmma::mem_row_major);
        __syncwarp();

        // lane: edge e, hidden units [half*8, half*8+8)
        float z = 0.0f;
        const float* crow = &sC[w][e*16 + half*8];
        const float* b1p  = &sb1[l*16 + half*8];
        const float* w2p  = &sw2[l*16 + half*8];
        #pragma unroll
        for (int i = 0; i < 8; i++) {
            float tv = fmaxf(crow[i] + b1p[i], 0.0f);
            z = fmaf(tv, w2p[i], z);
        }
        z += __shfl_xor_sync(0xffffffffu, z, 1);
        if (half == 0) {
            float ew = 1.0f / (1.0f + __expf(-(z + sb2[l])));
            g_ew[l*NE + pe] = ew;
            atomicAdd(&g_deg[dd*16 + l], ew);
        }
        __syncwarp();   // protect sC before next layer's store
    }
}

// scale ew by rsqrt(deg_src) ONLY (dst factor applied in k_agg); also re-zero g_cnt
__global__ void k_norm() {
    int p = blockIdx.x*256 + threadIdx.x;   // always < NE
    if (p < NN) g_cnt[p] = 0;               // restore invariant for next replay
    int s = g_csrc[p];
    float ds[16];
    const float4* sp = (const float4*)(g_deg + s*16);
    #pragma unroll
    for (int q = 0; q < 4; q++) {
        float4 v = sp[q];
        ds[4*q]=rsqrtf(v.x); ds[4*q+1]=rsqrtf(v.y);
        ds[4*q+2]=rsqrtf(v.z); ds[4*q+3]=rsqrtf(v.w);
    }
    #pragma unroll
    for (int l = 0; l < NL; l++)
        g_ew[l*NE + p] *= ds[l];
}

// ---------------- fused BN+ReLU + tensor-core GEMM (wmma m16n16k16) ----------------
// block = 256 threads (8 warps), 128 rows; each warp: 16 rows x 64 cols
__global__ __launch_bounds__(256) void k_gemm(
    const float* __restrict__ A, const float* __restrict__ W,
    __half* __restrict__ H, int slot)     // slot < 0 : no BN
{
    __shared__ __align__(32) __half sA[128*64];   // 16 KB, fp16 BN-relu'd A tile
    __shared__ __align__(32) __half sW[64*64];    // 8 KB,  fp16 weights (k-major [k][n])
    __shared__ __align__(32) float  sC[8][16*64]; // 32 KB, per-warp fp32 C staging
    __shared__ float smu[64], ssc[64];

    int t = threadIdx.x;
    int base = blockIdx.x*128;

    if (slot >= 0 && t < 64) {
        float mu  = g_colsum[slot*64 + t] * (1.0f/NN);
        float var = g_colsq[slot*64 + t] * (1.0f/NN) - mu*mu;
        if (var < 0.0f) var = 0.0f;
        smu[t] = mu;
        ssc[t] = rsqrtf(var + 1e-5f);
    }
    // weights -> fp16 smem (no dependence on smu)
    {
        const float4* W4 = (const float4*)W;
        for (int i = t; i < 1024; i += 256) {
            float4 v = W4[i];
            __half2 h0 = __floats2half2_rn(v.x, v.y);
            __half2 h1 = __floats2half2_rn(v.z, v.w);
            uint2 u; u.x = *(unsigned*)&h0; u.y = *(unsigned*)&h1;
            *(uint2*)(sW + i*4) = u;
        }
    }
    __syncthreads();   // smu ready for A staging

    // stage A tile: BN+ReLU+fp16 via float4 loads (8 per thread)
    {
        const float4* A4 = (const float4*)A;
        const int maxi = ((NN - base < 128 ? NN - base : 128) * 64) >> 2;  // valid float4s
        for (int i = t; i < 2048; i += 256) {
            float4 v;
            if (i < maxi) v = A4[(size_t)base*16 + i];
            else { v.x = v.y = v.z = v.w = 0.0f; }
            if (slot >= 0) {
                int c = (i & 15)*4;
                v.x = fmaxf((v.x - smu[c+0]) * ssc[c+0], 0.0f);
                v.y = fmaxf((v.y - smu[c+1]) * ssc[c+1], 0.0f);
                v.z = fmaxf((v.z - smu[c+2]) * ssc[c+2], 0.0f);
                v.w = fmaxf((v.w - smu[c+3]) * ssc[c+3], 0.0f);
            }
            __half2 h0 = __floats2half2_rn(v.x, v.y);
            __half2 h1 = __floats2half2_rn(v.z, v.w);
            uint2 u; u.x = *(unsigned*)&h0; u.y = *(unsigned*)&h1;
            *(uint2*)(sA + i*4) = u;
        }
    }
    __syncthreads();

    int w = t >> 5;
    int lane = t & 31;

    wmma::fragment<wmma::accumulator, 16, 16, 16, float> acc[4];
    #pragma unroll
    for (int n = 0; n < 4; n++) wmma::fill_fragment(acc[n], 0.0f);

    #pragma unroll
    for (int k = 0; k < 4; k++) {
        wmma::fragment<wmma::matrix_a, 16, 16, 16, __half, wmma::row_major> af;
        wmma::load_matrix_sync(af, sA + (w*16)*64 + k*16, 64);
        #pragma unroll
        for (int n = 0; n < 4; n++) {
            wmma::fragment<wmma::matrix_b, 16, 16, 16, __half, wmma::row_major> bf;
            wmma::load_matrix_sync(bf, sW + (k*16)*64 + n*16, 64);
            wmma::mma_sync(acc[n], af, bf, acc[n]);
        }
    }

    // stage fp32 -> smem (per-warp private region), then fp16 coalesced store
    #pragma unroll
    for (int n = 0; n < 4; n++)
        wmma::store_matrix_sync(&sC[w][n*16], acc[n], 64, wmma::mem_row_major);

    int wrow = base + w*16;
    if (wrow < NN) {   // NN % 16 == 0, so warp tiles are all-or-nothing
        __half2* H2 = (__half2*)(H + (size_t)wrow*64);
        #pragma unroll
        for (int i = lane; i < 512; i += 32) {
            float x0 = sC[w][2*i], x1 = sC[w][2*i+1];
            H2[i] = __floats2half2_rn(x0, x1);
        }
    }
}

// ---------------- BN statistics (standalone; fp32 partials -> float atomics) ----------------
__global__ void k_bnstats(const float* __restrict__ A, int slot) {
    int t = threadIdx.x;
    int c = t & 63, rg = t >> 6;              // 256 threads: 4 row lanes x 64 cols
    float s = 0.0f, q = 0.0f;                 // ~49 elements per thread: fp32 is exact enough
    for (int r = blockIdx.x*4 + rg; r < NN; r += gridDim.x*4) {
        float v = A[r*64 + c];
        s += v; q = fmaf(v, v, q);
    }
    __shared__ float ss[256], sq[256];
    ss[t] = s; sq[t] = q; __syncthreads();
    if (t < 64) {
        float S = ss[t] + ss[t+64] + ss[t+128] + ss[t+192];
        float Q = sq[t] + sq[t+64] + sq[t+128] + sq[t+192];
        atomicAdd(&g_colsum[slot*64 + c], S);
        atomicAdd(&g_colsq [slot*64 + c], Q);
    }
}

// ---------------- CSR aggregation: LDG.128 gathers + fused elementwise epilogues ----------
// lane = (edge slot 0-3)*8 + (col group 0-7); each lane covers 8 fp16 cols.
// weights in nrm are ew*dis_src; self term weight dv (seeded by eg==0 ONLY);
// final result = dv*sum + bias, dv = rsqrt(deg_dst).
__global__ __launch_bounds__(256) void k_agg(
    const __half* __restrict__ h, const float* __restrict__ nrm,
    int layer, const float* __restrict__ bias,
    float* __restrict__ cur, float* __restrict__ acc,
    const int* __restrict__ batch, int mode)
{
    int t = threadIdx.x;
    int w = (blockIdx.x*256 + t) >> 5;     // < NN always (exact grid)
    int lane = t & 31;
    int eg = lane >> 3;          // edge slot 0..3
    int cg = lane & 7;           // col group 0..7
    int cbase = cg*8;

    float dv = rsqrtf(g_deg[w*16 + layer]);   // dis_dst

    float a[8] = {0,0,0,0,0,0,0,0};
    if (eg == 0) {   // self term seeded ONCE (reduction sums over the 4 edge slots)
        uint4 hv = *(const uint4*)(h + (size_t)w*64 + cbase);
        const __half2* hh = (const __half2*)&hv;
        #pragma unroll
        for (int i = 0; i < 4; i++) {
            float2 f = __half22float2(hh[i]);
            a[2*i]   = dv * f.x;
            a[2*i+1] = dv * f.y;
        }
    }

    int p0 = g_rowptr[w], p1 = g_rowptr[w+1];
    for (int p = p0; p < p1; p += 4) {
        int ei = p + eg;
        bool valid = (ei < p1);
        int eidx = valid ? ei : p;
        float wt = nrm[eidx];
        if (!valid) wt = 0.0f;
        int s = g_csrc[eidx];
        uint4 hv = *(const uint4*)(h + (size_t)s*64 + cbase);
        const __half2* hh = (const __half2*)&hv;
        #pragma unroll
        for (int i = 0; i < 4; i++) {
            float2 f = __half22float2(hh[i]);
            a[2*i]   = fmaf(wt, f.x, a[2*i]);
            a[2*i+1] = fmaf(wt, f.y, a[2*i+1]);
        }
    }

    // reduce across the 4 edge slots (lanes cg, cg+8, cg+16, cg+24)
    #pragma unroll
    for (int i = 0; i < 8; i++) {
        a[i] += __shfl_xor_sync(0xffffffffu, a[i], 8);
        a[i] += __shfl_xor_sync(0xffffffffu, a[i], 16);
    }

    if (lane < 8) {
        float4 b0 = *(const float4*)(bias + cbase);
        float4 b1 = *(const float4*)(bias + cbase + 4);
        float o[8];
        o[0] = fmaf(dv, a[0], b0.x); o[1] = fmaf(dv, a[1], b0.y);
        o[2] = fmaf(dv, a[2], b0.z); o[3] = fmaf(dv, a[3], b0.w);
        o[4] = fmaf(dv, a[4], b1.x); o[5] = fmaf(dv, a[5], b1.y);
        o[6] = fmaf(dv, a[6], b1.z); o[7] = fmaf(dv, a[7], b1.w);

        size_t off = (size_t)w*64 + cbase;
        if (mode & M_SKIP) {
            float4 s0 = *(float4*)(acc + off);
            float4 s1 = *(float4*)(acc + off + 4);
            o[0] += s0.x; o[1] += s0.y; o[2] += s0.z; o[3] += s0.w;
            o[4] += s1.x; o[5] += s1.y; o[6] += s1.z; o[7] += s1.w;
            s0.x += o[0]; s0.y += o[1]; s0.z += o[2]; s0.w += o[3];
            s1.x += o[4]; s1.y += o[5]; s1.z += o[6]; s1.w += o[7];
            *(float4*)(acc + off)     = s0;
            *(float4*)(acc + off + 4) = s1;
        }
        float4 c0, c1;
        c0.x=o[0]; c0.y=o[1]; c0.z=o[2]; c0.w=o[3];
        c1.x=o[4]; c1.y=o[5]; c1.z=o[6]; c1.w=o[7];
        *(float4*)(cur + off)     = c0;
        *(float4*)(cur + off + 4) = c1;
        if (mode & M_COPY) {
            *(float4*)(acc + off)     = c0;
            *(float4*)(acc + off + 4) = c1;
        }
        if (mode & M_POOL) {
            int b = batch[w];
            #pragma unroll
            for (int i = 0; i < 8; i++) {
                float rv = fmaxf(o[i], 0.0f);
                atomicMax((int*)&g_pool[b*64 + cbase + i], __float_as_int(rv));
            }
        }
    }
}

// ---------------- readout ----------------
__global__ void k_final(const float* __restrict__ linW, const float* __restrict__ linb,
                        float* __restrict__ out) {
    int g = blockIdx.x*blockDim.x + threadIdx.x;
    if (g >= NG) return;
    float a0 = linb[0], a1 = linb[1];
    #pragma unroll 8
    for (int c = 0; c < CC; c++) {
        float v = g_pool[g*64 + c];
        a0 = fmaf(v, linW[c*2+0], a0);
        a1 = fmaf(v, linW[c*2+1], a1);
    }
    out[g*2+0] = a0;
    out[g*2+1] = a1;
}

// ---------------- launch ----------------
extern "C" void kernel_launch(void* const* d_in, const int* in_sizes, int n_in,
                              void* d_out, int out_size)
{
    const float* x     = (const float*)d_in[0];
    const int*   ei    = (const int*)  d_in[1];
    const int*   batch = (const int*)  d_in[2];
    /* d_in[3] = dropout (unused, eval mode) */
    const float* ea    = (const float*)d_in[4];
    const float* Wlin1 = (const float*)d_in[5];
    const float* bias1 = (const float*)d_in[6];
    const float* m1W1  = (const float*)d_in[7];
    const float* m1b1  = (const float*)d_in[8];
    const float* m2W1  = (const float*)d_in[9];
    const float* m2b1  = (const float*)d_in[10];
    const float* hWlin = (const float*)d_in[11];
    const float* hbias = (const float*)d_in[12];
    const float* hm1W  = (const float*)d_in[13];
    const float* hm1b  = (const float*)d_in[14];
    const float* hm2W  = (const float*)d_in[15];
    const float* hm2b  = (const float*)d_in[16];
    const float* linW  = (const float*)d_in[17];
    const float* linb  = (const float*)d_in[18];
    float* out = (float*)d_out;

    const int* src = ei;
    const int* dst = ei + NE;

    __half *p_h;
    float *p_cur, *p_acc, *p_ew;
    cudaGetSymbolAddress((void**)&p_h,   g_h);
    cudaGetSymbolAddress((void**)&p_cur, g_cur);
    cudaGetSymbolAddress((void**)&p_acc, g_acc);
    cudaGetSymbolAddress((void**)&p_ew,  g_ew);

    const int EB = NE / 256;                  // 3125 (exact)
    const int MB = NE / (16*8);               // 6250 blocks: 8 warps x 16-edge tiles
    const int GB = (NN + 127) / 128;          // 391 (gemm, 128 rows/block)
    const int AB = (NN*32) / 256;             // 6250 (exact -> 50000 warps = NN)

    // prologue: CSR + all edge norms for all 13 layers
    k_hist   <<<EB, 256>>>(dst);              // also inits g_deg=1.0
    k_scanall<<<1, 1024>>>();                 // also zeroes pool + BN stats
    k_scatter<<<EB, 256>>>(src, dst);
    k_edgemlp<<<MB, 256>>>(ea, m1W1, m1b1, m2W1, m2b1, hm1W, hm1b, hm2W, hm2b);
    k_norm   <<<EB, 256>>>();                 // rsqrt on the fly; also re-zeroes g_cnt

    // conv1
    k_gemm<<<GB, 256>>>(x, Wlin1, p_h, -1);
    k_agg <<<AB, 256>>>(p_h, p_ew, 0, bias1, p_cur, p_acc, batch, M_COPY);

    // 12 hidden convs (6 blocks x 2)
    for (int j = 0; j < 12; j++) {
        int l = j + 1;
        k_bnstats<<<256, 256>>>(p_cur, j);
        k_gemm<<<GB, 256>>>(p_cur, hWlin + j*CC*CC, p_h, j);
        int mode;
        if (j == 11)      mode = M_SKIP | M_POOL;   // last: skip + relu + pool
        else if (j & 1)   mode = M_SKIP;            // end of block: dense skip
        else              mode = 0;
        k_agg <<<AB, 256>>>(p_h, p_ew + l*NE, l, hbias + j*CC, p_cur, p_acc, batch, mode);
    }

    k_final<<<(NG + 63)/64, 64>>>(linW, linb, out);
}